// round 4
// baseline (speedup 1.0000x reference)
#include <cuda_runtime.h>
#include <cuda_bf16.h>

// 3x3 median blur, zero padding, 48 planes of 512x512 fp32.
// R4: 8 outputs per thread (one row). 10 columns sorted once, 8 overlapping
// merges. Loads: 4 aligned LDG.128 per row (x0-4, x0, x0+4, x0+8) -> 24 B of
// L1 traffic per output (was 36), column-sort cost amortized over 8 outputs.

constexpr int W = 512;
constexpr int H = 512;

__device__ __forceinline__ float med3f(float a, float b, float c) {
    return fmaxf(fminf(a, b), fminf(fmaxf(a, b), c));
}

#define CE(a, b) do { float _t = fminf(a, b); (b) = fmaxf(a, b); (a) = _t; } while (0)

__global__ void __launch_bounds__(512) median3x3_kernel(
    const float* __restrict__ in, float* __restrict__ out)
{
    const int plane = blockIdx.y;                              // 0..47
    const int y     = blockIdx.x * blockDim.y + threadIdx.y;   // 0..511
    const int x0    = threadIdx.x * 8;                         // 0..504

    const float* p = in  + (size_t)plane * (H * W) + (size_t)y * W;
    float*       q = out + (size_t)plane * (H * W) + (size_t)y * W;

    const bool has_l = (x0 > 0);
    const bool has_r = (x0 + 8 < W);
    const float4 z4 = make_float4(0.f, 0.f, 0.f, 0.f);

    // r[dy][i] : row y-1+dy, column x0-1+i  (i = 0..9)
    float r[3][10];
    #pragma unroll
    for (int dy = 0; dy < 3; dy++) {
        const int yy = y + dy - 1;
        if (yy < 0 || yy >= H) {
            #pragma unroll
            for (int i = 0; i < 10; i++) r[dy][i] = 0.0f;
        } else {
            const float* row = p + (dy - 1) * W;
            const float4 L  = has_l ? *reinterpret_cast<const float4*>(row + x0 - 4) : z4;
            const float4 C0 =         *reinterpret_cast<const float4*>(row + x0);
            const float4 C1 =         *reinterpret_cast<const float4*>(row + x0 + 4);
            const float4 R  = has_r ? *reinterpret_cast<const float4*>(row + x0 + 8) : z4;
            r[dy][0] = L.w;
            r[dy][1] = C0.x; r[dy][2] = C0.y; r[dy][3] = C0.z; r[dy][4] = C0.w;
            r[dy][5] = C1.x; r[dy][6] = C1.y; r[dy][7] = C1.z; r[dy][8] = C1.w;
            r[dy][9] = R.x;
        }
    }

    // Sort each column of 3: lo <= mi <= hi
    float lo[10], mi[10], hi[10];
    #pragma unroll
    for (int i = 0; i < 10; i++) {
        float a = r[0][i], b = r[1][i], c = r[2][i];
        CE(a, b); CE(b, c); CE(a, b);
        lo[i] = a; mi[i] = b; hi[i] = c;
    }

    // 8 outputs from overlapping column triples
    float res[8];
    #pragma unroll
    for (int j = 0; j < 8; j++) {
        const float mx = fmaxf(fmaxf(lo[j], lo[j + 1]), lo[j + 2]);
        const float mn = fminf(fminf(hi[j], hi[j + 1]), hi[j + 2]);
        const float md = med3f(mi[j], mi[j + 1], mi[j + 2]);
        res[j] = med3f(mx, md, mn);
    }

    float4 o0, o1;
    o0.x = res[0]; o0.y = res[1]; o0.z = res[2]; o0.w = res[3];
    o1.x = res[4]; o1.y = res[5]; o1.z = res[6]; o1.w = res[7];
    *reinterpret_cast<float4*>(q + x0)     = o0;
    *reinterpret_cast<float4*>(q + x0 + 4) = o1;
}

extern "C" void kernel_launch(void* const* d_in, const int* in_sizes, int n_in,
                              void* d_out, int out_size)
{
    const float* in  = (const float*)d_in[0];
    float*       out = (float*)d_out;

    // Block: 64 x-groups (8 px each) x 8 rows -> 512x8 output tile, 512 thr.
    dim3 block(64, 8, 1);
    dim3 grid(512 / 8, 48, 1);
    median3x3_kernel<<<grid, block>>>(in, out);
}

// round 5
// speedup vs baseline: 1.2150x; 1.2150x over previous
#include <cuda_runtime.h>
#include <cuda_bf16.h>

// 3x3 median blur, zero padding, 48 planes of 512x512 fp32.
// R5: R1's proven horizontal layout (4-wide, LDG.128 + 2 scalar halos) with a
// 4-tall rolling register window: 6 row-loads serve 4 output rows, halving
// per-output L1 traffic (2.25 -> 1.125 loads/out) at identical alu cost.

constexpr int W = 512;
constexpr int H = 512;
constexpr int TILE_H = 4;

__device__ __forceinline__ float med3f(float a, float b, float c) {
    return fmaxf(fminf(a, b), fminf(fmaxf(a, b), c));
}

#define CE(a, b) do { float _t = fminf(a, b); (b) = fmaxf(a, b); (a) = _t; } while (0)

// Load 6 columns [x0-1 .. x0+4] of row yy into c (zeros outside the plane).
__device__ __forceinline__ void load6(float c[6], const float* __restrict__ pb,
                                      int yy, int x0) {
    if (yy < 0 || yy >= H) {
        #pragma unroll
        for (int i = 0; i < 6; i++) c[i] = 0.0f;
        return;
    }
    const float* row = pb + (size_t)yy * W;
    const float4 v = *reinterpret_cast<const float4*>(row + x0);
    c[1] = v.x; c[2] = v.y; c[3] = v.z; c[4] = v.w;
    c[0] = (x0 > 0)     ? __ldg(row + x0 - 1) : 0.0f;
    c[5] = (x0 + 4 < W) ? __ldg(row + x0 + 4) : 0.0f;
}

// Sort columns of the 3 rows, merge 4 overlapping triples, store one row.
__device__ __forceinline__ void window_store(const float r0[6], const float r1[6],
                                             const float r2[6],
                                             float* __restrict__ q) {
    float lo[6], mi[6], hi[6];
    #pragma unroll
    for (int i = 0; i < 6; i++) {
        float a = r0[i], b = r1[i], c = r2[i];
        CE(a, b); CE(b, c); CE(a, b);
        lo[i] = a; mi[i] = b; hi[i] = c;
    }
    float res[4];
    #pragma unroll
    for (int j = 0; j < 4; j++) {
        const float mx = fmaxf(fmaxf(lo[j], lo[j + 1]), lo[j + 2]);
        const float mn = fminf(fminf(hi[j], hi[j + 1]), hi[j + 2]);
        const float md = med3f(mi[j], mi[j + 1], mi[j + 2]);
        res[j] = med3f(mx, md, mn);
    }
    float4 o;
    o.x = res[0]; o.y = res[1]; o.z = res[2]; o.w = res[3];
    *reinterpret_cast<float4*>(q) = o;
}

__global__ void __launch_bounds__(512) median3x3_kernel(
    const float* __restrict__ in, float* __restrict__ out)
{
    const int plane = blockIdx.y;                                   // 0..47
    const int x0    = threadIdx.x * 4;                              // 0..508
    const int y0    = (blockIdx.x * TILE_H + threadIdx.y) * TILE_H; // top output row

    const float* pb = in  + (size_t)plane * (H * W);
    float*       qb = out + (size_t)plane * (H * W) + (size_t)y0 * W + x0;

    // Rolling 3-row window in registers: rows y0-1, y0, y0+1 to start.
    float rows[3][6];
    load6(rows[0], pb, y0 - 1, x0);
    load6(rows[1], pb, y0,     x0);
    load6(rows[2], pb, y0 + 1, x0);

    #pragma unroll
    for (int t = 0; t < TILE_H; t++) {
        window_store(rows[t % 3], rows[(t + 1) % 3], rows[(t + 2) % 3],
                     qb + (size_t)t * W);
        if (t < TILE_H - 1)
            load6(rows[t % 3], pb, y0 + t + 2, x0);  // overwrite oldest row
    }
}

extern "C" void kernel_launch(void* const* d_in, const int* in_sizes, int n_in,
                              void* d_out, int out_size)
{
    const float* in  = (const float*)d_in[0];
    float*       out = (float*)d_out;

    // Block: 128 x-groups (4 px) x 4 tile-rows -> 512x16 output region/block.
    dim3 block(128, 4, 1);
    dim3 grid(512 / (TILE_H * 4), 48, 1);
    median3x3_kernel<<<grid, block>>>(in, out);
}